// round 1
// baseline (speedup 1.0000x reference)
#include <cuda_runtime.h>

#define BATCH 32
#define SEQ   16384
#define CIN   64
#define NF    64
#define KW    9
#define TOUT  (SEQ - KW + 1)   // 16376
#define TTILE 64

// w transposed to [k][c][f] so per-(k,c) filter reads are contiguous float4 over f.
__device__ float g_wt[KW * CIN * NF];

__global__ void transpose_w_kernel(const float* __restrict__ w) {
    int idx = blockIdx.x * blockDim.x + threadIdx.x;
    if (idx < NF * KW * CIN) {
        int f = idx / (KW * CIN);
        int k = (idx / CIN) % KW;
        int c = idx % CIN;
        g_wt[(k * CIN + c) * NF + f] = w[idx];
    }
}

__global__ __launch_bounds__(256) void conv1d_kernel(const float* __restrict__ x,
                                                     const float* __restrict__ bias,
                                                     float* __restrict__ out) {
    __shared__ float xs[TTILE + KW - 1][CIN];   // 72 x 64 fp32 = 18.4 KB

    const int t0 = blockIdx.x * TTILE;
    const int b  = blockIdx.y;
    const float* xb = x + (size_t)b * SEQ * CIN;

    // Stage x tile (rows t0 .. t0+71, zero-fill past SEQ). Fully coalesced.
    for (int i = threadIdx.x; i < (TTILE + KW - 1) * CIN; i += 256) {
        int r = i / CIN;
        int c = i % CIN;
        int t = t0 + r;
        xs[r][c] = (t < SEQ) ? xb[(size_t)t * CIN + c] : 0.0f;
    }
    __syncthreads();

    // 256 threads: 16 f-groups x 16 t-groups, each thread 4t x 4f micro-tile.
    const int tx  = threadIdx.x & 15;   // f group
    const int ty  = threadIdx.x >> 4;   // t group
    const int f0  = tx * 4;
    const int tl0 = ty * 4;

    float acc[4][4];
#pragma unroll
    for (int i = 0; i < 4; i++)
#pragma unroll
        for (int j = 0; j < 4; j++) acc[i][j] = 0.0f;

    // Implicit GEMM over K = 9 taps x 64 channels.
    // Per c: load 12 x-values once (smem broadcast), reuse across all 9 taps.
    for (int c = 0; c < CIN; c++) {
        float xr[TTILE / 16 + KW - 1];  // 12
#pragma unroll
        for (int r = 0; r < 12; r++) xr[r] = xs[tl0 + r][c];

#pragma unroll
        for (int k = 0; k < KW; k++) {
            const float4 wv = *(const float4*)&g_wt[(k * CIN + c) * NF + f0];
#pragma unroll
            for (int i = 0; i < 4; i++) {
                const float xv = xr[i + k];
                acc[i][0] += xv * wv.x;
                acc[i][1] += xv * wv.y;
                acc[i][2] += xv * wv.z;
                acc[i][3] += xv * wv.w;
            }
        }
    }

    const float4 bv = *(const float4*)(bias + f0);
#pragma unroll
    for (int i = 0; i < 4; i++) {
        int t = t0 + tl0 + i;
        if (t < TOUT) {
            float4 o;
            o.x = acc[i][0] + bv.x;
            o.y = acc[i][1] + bv.y;
            o.z = acc[i][2] + bv.z;
            o.w = acc[i][3] + bv.w;
            *(float4*)&out[((size_t)b * TOUT + t) * NF + f0] = o;
        }
    }
}

extern "C" void kernel_launch(void* const* d_in, const int* in_sizes, int n_in,
                              void* d_out, int out_size) {
    const float* x    = (const float*)d_in[0];   // [32,16384,64]
    const float* w    = (const float*)d_in[1];   // [64,9,64]
    const float* bias = (const float*)d_in[2];   // [64]
    float* out = (float*)d_out;                  // [32,16376,64]

    transpose_w_kernel<<<(NF * KW * CIN + 255) / 256, 256>>>(w);

    dim3 grid((TOUT + TTILE - 1) / TTILE, BATCH);  // 256 x 32
    conv1d_kernel<<<grid, 256>>>(x, bias, out);
}

// round 4
// speedup vs baseline: 7.1411x; 7.1411x over previous
#include <cuda_runtime.h>
#include <cuda_fp16.h>
#include <cstdint>

#define BATCH 32
#define SEQ   16384
#define CIN   64
#define NF    64
#define KW    9
#define TOUT  (SEQ - KW + 1)          // 16376
#define TTILE 128
#define TILES_PER_B 128
#define NTILES (BATCH * TILES_PER_B)  // 4096
#define XROWS (TTILE + KW - 1)        // 136

// smem layout (from 1024B-aligned base)
#define WS_OFF    0
#define WS_BYTES  (KW * 64 * 128)           // 73728: 9 taps of [64c x 128B(64f fp16)] SW128
#define XS_OFF    WS_BYTES                  // 73728 (1024-aligned)
#define XS_BYTES  (XROWS * 128)             // 17408: 136 rows x 64 fp16, SW128
#define BIAS_OFF  (XS_OFF + XS_BYTES)       // 91136
#define SMEM_BYTES (BIAS_OFF + 256 + 1024)  // 92416 (incl. align slack) -> 2 CTAs/SM

__device__ __align__(16) unsigned char wt_img[WS_BYTES];

static __device__ __forceinline__ uint32_t swz(uint32_t o) { return o ^ ((o >> 3) & 0x70); }

static __device__ __forceinline__ uint32_t smem_u32(const void* p) {
    uint32_t a;
    asm("{ .reg .u64 t; cvta.to.shared.u64 t, %1; cvt.u32.u64 %0, t; }" : "=r"(a) : "l"(p));
    return a;
}

static __device__ __forceinline__ void ldsm_x4(uint32_t& r0, uint32_t& r1, uint32_t& r2, uint32_t& r3, uint32_t addr) {
    asm volatile("ldmatrix.sync.aligned.m8n8.x4.shared.b16 {%0,%1,%2,%3}, [%4];"
                 : "=r"(r0), "=r"(r1), "=r"(r2), "=r"(r3) : "r"(addr));
}
static __device__ __forceinline__ void ldsm_x4t(uint32_t& r0, uint32_t& r1, uint32_t& r2, uint32_t& r3, uint32_t addr) {
    asm volatile("ldmatrix.sync.aligned.m8n8.x4.trans.shared.b16 {%0,%1,%2,%3}, [%4];"
                 : "=r"(r0), "=r"(r1), "=r"(r2), "=r"(r3) : "r"(addr));
}
static __device__ __forceinline__ void mma16816(float* d, const uint32_t* a, const uint32_t* b) {
    asm volatile("mma.sync.aligned.m16n8k16.row.col.f32.f16.f16.f32 "
                 "{%0,%1,%2,%3}, {%4,%5,%6,%7}, {%8,%9}, {%0,%1,%2,%3};"
                 : "+f"(d[0]), "+f"(d[1]), "+f"(d[2]), "+f"(d[3])
                 : "r"(a[0]), "r"(a[1]), "r"(a[2]), "r"(a[3]), "r"(b[0]), "r"(b[1]));
}

// ---- prep: w fp32 [f][k][c] -> fp16 image [k][c][f], SW128-swizzled per 8KB tap tile
__global__ void prep_w_kernel(const float* __restrict__ w) {
    int i = blockIdx.x * 256 + threadIdx.x;
    if (i < NF * KW * CIN) {
        int f = i / (KW * CIN);
        int k = (i / CIN) % CIN ? (i / CIN) % KW : (i / CIN) % KW;  // (i/CIN)%KW
        k = (i / CIN) % KW;
        int c = i % CIN;
        *reinterpret_cast<__half*>(wt_img + k * 8192 + swz((uint32_t)(c * 128 + f * 2))) = __float2half_rn(w[i]);
    }
}

// ---- main persistent kernel -------------------------------------------------
__global__ __launch_bounds__(256, 2) void conv_hmma_kernel(const float* __restrict__ x,
                                                           const float* __restrict__ bias,
                                                           float* __restrict__ out) {
    extern __shared__ char smem_raw[];
    const uint32_t raw = smem_u32(smem_raw);
    const uint32_t sb  = (raw + 1023u) & ~1023u;
    char* base = smem_raw + (sb - raw);
    const int tid  = threadIdx.x;
    const int lane = tid & 31;
    const int wid  = tid >> 5;
    const int warp_m = wid & 3;      // 4 warps over 128 rows (32 each)
    const int warp_n = wid >> 2;     // 2 warps over 64 f (32 each)

    // copy w image + bias into smem (once)
    for (int i = tid; i < WS_BYTES / 16; i += 256)
        *(uint4*)(base + WS_OFF + i * 16) = *(const uint4*)(wt_img + i * 16);
    if (tid < NF) *(float*)(base + BIAS_OFF + tid * 4) = bias[tid];
    __syncthreads();

    // per-lane ldmatrix address components
    const int row8   = (lane & 7) + ((lane >> 3) & 1) * 8;  // 0..15
    const int half16 = (lane >> 4);                          // 0/1
    // A: xs row = warp_m*32 + mt*16 + k + row8 ; col halves = cc*16 + half16*8
    const uint32_t a_base = (uint32_t)(row8 * 128 + half16 * 16);
    // B: ws row c = cc*16 + row8 ; col f = warp_n*32 + p*16 + half16*8
    const uint32_t b_base = (uint32_t)(row8 * 128 + (warp_n * 32 + half16 * 8) * 2);

    const int g  = lane >> 2;
    const int tg = lane & 3;

    for (int tile = blockIdx.x; tile < NTILES; tile += gridDim.x) {
        const int b  = tile >> 7;
        const int t0 = (tile & 127) << 7;
        const float* xb = x + ((size_t)b << 20);

        // ---- stage x tile -> fp16 SW128 smem
        for (int q = tid; q < XROWS * 8; q += 256) {
            const int r = q >> 3, c0 = (q & 7) << 3;
            char* dst = base + XS_OFF + swz((uint32_t)(r * 128 + c0 * 2));
            const int t = t0 + r;
            uint4 v;
            if (t < SEQ) {
                const float4 a0 = *(const float4*)(xb + (size_t)t * CIN + c0);
                const float4 a1 = *(const float4*)(xb + (size_t)t * CIN + c0 + 4);
                __half2 h0 = __floats2half2_rn(a0.x, a0.y);
                __half2 h1 = __floats2half2_rn(a0.z, a0.w);
                __half2 h2 = __floats2half2_rn(a1.x, a1.y);
                __half2 h3 = __floats2half2_rn(a1.z, a1.w);
                v.x = *(uint32_t*)&h0; v.y = *(uint32_t*)&h1;
                v.z = *(uint32_t*)&h2; v.w = *(uint32_t*)&h3;
            } else {
                v = make_uint4(0u, 0u, 0u, 0u);
            }
            *(uint4*)dst = v;
        }
        __syncthreads();

        // ---- 36 K-steps of m16n8k16 HMMA
        float acc[2][4][4];
#pragma unroll
        for (int mt = 0; mt < 2; mt++)
#pragma unroll
            for (int nt = 0; nt < 4; nt++)
#pragma unroll
                for (int j = 0; j < 4; j++) acc[mt][nt][j] = 0.0f;

        const uint32_t xs_addr = sb + XS_OFF;
        const uint32_t ws_addr = sb + WS_OFF;

        for (int k = 0; k < KW; k++) {
            const uint32_t a_row0 = (uint32_t)((warp_m * 32 + k) * 128);
            const uint32_t w_tap  = ws_addr + k * 8192;
#pragma unroll
            for (int cc = 0; cc < 4; cc++) {
                uint32_t af[2][4];
#pragma unroll
                for (int mt = 0; mt < 2; mt++) {
                    const uint32_t off = a_row0 + (uint32_t)(mt * 16 * 128) + (uint32_t)(cc * 32) + a_base;
                    ldsm_x4(af[mt][0], af[mt][1], af[mt][2], af[mt][3], xs_addr + swz(off));
                }
                uint32_t bf[4][2];
#pragma unroll
                for (int p = 0; p < 2; p++) {
                    const uint32_t off = (uint32_t)(cc * 16 * 128) + (uint32_t)(p * 16 * 2) + b_base;
                    uint32_t r0, r1, r2, r3;
                    ldsm_x4t(r0, r1, r2, r3, w_tap + swz(off));
                    bf[p * 2 + 0][0] = r0; bf[p * 2 + 0][1] = r1;
                    bf[p * 2 + 1][0] = r2; bf[p * 2 + 1][1] = r3;
                }
#pragma unroll
                for (int mt = 0; mt < 2; mt++)
#pragma unroll
                    for (int nt = 0; nt < 4; nt++)
                        mma16816(acc[mt][nt], af[mt], bf[nt]);
            }
        }
        __syncthreads();   // all warps done reading xs before next stage

        // ---- epilogue: bias + direct STG
#pragma unroll
        for (int mt = 0; mt < 2; mt++) {
            const int trow = t0 + warp_m * 32 + mt * 16 + g;
#pragma unroll
            for (int half = 0; half < 2; half++) {
                const int t = trow + half * 8;
                if (t < TOUT) {
                    float* o = out + ((size_t)b * TOUT + t) * NF;
#pragma unroll
                    for (int nt = 0; nt < 4; nt++) {
                        const int f = warp_n * 32 + nt * 8 + tg * 2;
                        const float2 bv = *(const float2*)(base + BIAS_OFF + f * 4);
                        float2 v;
                        v.x = acc[mt][nt][half * 2 + 0] + bv.x;
                        v.y = acc[mt][nt][half * 2 + 1] + bv.y;
                        *(float2*)(o + f) = v;
                    }
                }
            }
        }
    }
}

extern "C" void kernel_launch(void* const* d_in, const int* in_sizes, int n_in,
                              void* d_out, int out_size) {
    const float* x    = (const float*)d_in[0];
    const float* w    = (const float*)d_in[1];
    const float* bias = (const float*)d_in[2];
    float* out = (float*)d_out;

    cudaFuncSetAttribute(conv_hmma_kernel, cudaFuncAttributeMaxDynamicSharedMemorySize, SMEM_BYTES);

    prep_w_kernel<<<(NF * KW * CIN + 255) / 256, 256>>>(w);
    conv_hmma_kernel<<<296, 256, SMEM_BYTES>>>(x, bias, out);
}

// round 6
// speedup vs baseline: 7.3628x; 1.0311x over previous
#include <cuda_runtime.h>
#include <cuda_fp16.h>
#include <cstdint>

#define BATCH 32
#define SEQ   16384
#define CIN   64
#define NF    64
#define KW    9
#define TOUT  (SEQ - KW + 1)          // 16376
#define TTILE 256
#define TILES_PER_B 64                // ceil(16376/256)
#define NTILES (BATCH * TILES_PER_B)  // 2048
#define XROWS (TTILE + KW - 1)        // 264

// smem layout (from 1024B-aligned base)
#define WS_OFF    0
#define WS_BYTES  (KW * 64 * 128)           // 73728: 9 taps of [64c x 128B(64f fp16)] SW128
#define XS_OFF    WS_BYTES                  // 73728 (1024-aligned)
#define XS_BYTES  (XROWS * 128)             // 33792: 264 rows x 64 fp16, SW128
#define BIAS_OFF  (XS_OFF + XS_BYTES)       // 107520
#define SMEM_BYTES (BIAS_OFF + 256 + 1024)  // 108800 -> 2 CTAs/SM

__device__ __align__(16) unsigned char wt_img[WS_BYTES];

static __device__ __forceinline__ uint32_t swz(uint32_t o) { return o ^ ((o >> 3) & 0x70); }

static __device__ __forceinline__ uint32_t smem_u32(const void* p) {
    uint32_t a;
    asm("{ .reg .u64 t; cvta.to.shared.u64 t, %1; cvt.u32.u64 %0, t; }" : "=r"(a) : "l"(p));
    return a;
}

static __device__ __forceinline__ void ldsm_x4(uint32_t& r0, uint32_t& r1, uint32_t& r2, uint32_t& r3, uint32_t addr) {
    asm volatile("ldmatrix.sync.aligned.m8n8.x4.shared.b16 {%0,%1,%2,%3}, [%4];"
                 : "=r"(r0), "=r"(r1), "=r"(r2), "=r"(r3) : "r"(addr));
}
static __device__ __forceinline__ void ldsm_x4t(uint32_t& r0, uint32_t& r1, uint32_t& r2, uint32_t& r3, uint32_t addr) {
    asm volatile("ldmatrix.sync.aligned.m8n8.x4.trans.shared.b16 {%0,%1,%2,%3}, [%4];"
                 : "=r"(r0), "=r"(r1), "=r"(r2), "=r"(r3) : "r"(addr));
}
static __device__ __forceinline__ void mma16816(float* d, const uint32_t* a, const uint32_t* b) {
    asm volatile("mma.sync.aligned.m16n8k16.row.col.f32.f16.f16.f32 "
                 "{%0,%1,%2,%3}, {%4,%5,%6,%7}, {%8,%9}, {%0,%1,%2,%3};"
                 : "+f"(d[0]), "+f"(d[1]), "+f"(d[2]), "+f"(d[3])
                 : "r"(a[0]), "r"(a[1]), "r"(a[2]), "r"(a[3]), "r"(b[0]), "r"(b[1]));
}

// ---- prep: w fp32 [f][k][c] -> fp16 image [k][c][f], SW128-swizzled per 8KB tap tile
__global__ void prep_w_kernel(const float* __restrict__ w) {
    int i = blockIdx.x * 256 + threadIdx.x;
    if (i < NF * KW * CIN) {
        int f = i / (KW * CIN);
        int k = (i / CIN) % KW;
        int c = i % CIN;
        *reinterpret_cast<__half*>(wt_img + k * 8192 + swz((uint32_t)(c * 128 + f * 2))) = __float2half_rn(w[i]);
    }
}

// ---- main persistent kernel -------------------------------------------------
__global__ __launch_bounds__(256, 2) void conv_hmma_kernel(const float* __restrict__ x,
                                                           const float* __restrict__ bias,
                                                           float* __restrict__ out) {
    extern __shared__ char smem_raw[];
    const uint32_t raw = smem_u32(smem_raw);
    const uint32_t sb  = (raw + 1023u) & ~1023u;
    char* base = smem_raw + (sb - raw);
    const int tid  = threadIdx.x;
    const int lane = tid & 31;
    const int wid  = tid >> 5;
    const int warp_m = wid & 3;      // 4 warps over 256 rows (64 each)
    const int warp_n = wid >> 2;     // 2 warps over 64 f (32 each)

    // copy w image + bias into smem (once)
    for (int i = tid; i < WS_BYTES / 16; i += 256)
        *(uint4*)(base + WS_OFF + i * 16) = *(const uint4*)(wt_img + i * 16);
    if (tid < NF) *(float*)(base + BIAS_OFF + tid * 4) = bias[tid];
    __syncthreads();

    // per-lane ldmatrix address components
    const int row8   = (lane & 7) + ((lane >> 3) & 1) * 8;  // 0..15
    const int half16 = (lane >> 4);                          // 0/1
    const uint32_t a_base = (uint32_t)(row8 * 128 + half16 * 16);
    const uint32_t b_base = (uint32_t)(row8 * 128 + (warp_n * 32 + half16 * 8) * 2);

    const int g  = lane >> 2;
    const int tg = lane & 3;

    for (int tile = blockIdx.x; tile < NTILES; tile += gridDim.x) {
        const int b  = tile >> 6;
        const int t0 = (tile & 63) << 8;
        const float* xb = x + ((size_t)b << 20);

        // ---- stage x tile -> fp16 SW128 smem (264 rows)
        for (int q = tid; q < XROWS * 8; q += 256) {
            const int r = q >> 3, c0 = (q & 7) << 3;
            char* dst = base + XS_OFF + swz((uint32_t)(r * 128 + c0 * 2));
            const int t = t0 + r;
            uint4 v;
            if (t < SEQ) {
                const float4 a0 = *(const float4*)(xb + (size_t)t * CIN + c0);
                const float4 a1 = *(const float4*)(xb + (size_t)t * CIN + c0 + 4);
                __half2 h0 = __floats2half2_rn(a0.x, a0.y);
                __half2 h1 = __floats2half2_rn(a0.z, a0.w);
                __half2 h2 = __floats2half2_rn(a1.x, a1.y);
                __half2 h3 = __floats2half2_rn(a1.z, a1.w);
                v.x = *(uint32_t*)&h0; v.y = *(uint32_t*)&h1;
                v.z = *(uint32_t*)&h2; v.w = *(uint32_t*)&h3;
            } else {
                v = make_uint4(0u, 0u, 0u, 0u);
            }
            *(uint4*)dst = v;
        }
        __syncthreads();

        // ---- 36 K-steps of m16n8k16 HMMA, warp tile 64r x 32f
        float acc[4][4][4];
#pragma unroll
        for (int mt = 0; mt < 4; mt++)
#pragma unroll
            for (int nt = 0; nt < 4; nt++)
#pragma unroll
                for (int j = 0; j < 4; j++) acc[mt][nt][j] = 0.0f;

        const uint32_t xs_addr = sb + XS_OFF;
        const uint32_t ws_addr = sb + WS_OFF;

        for (int k = 0; k < KW; k++) {
            const uint32_t a_row0 = (uint32_t)((warp_m * 64 + k) * 128);
            const uint32_t w_tap  = ws_addr + k * 8192;
#pragma unroll
            for (int cc = 0; cc < 4; cc++) {
                uint32_t bf[4][2];
#pragma unroll
                for (int p = 0; p < 2; p++) {
                    const uint32_t off = (uint32_t)(cc * 16 * 128) + (uint32_t)(p * 16 * 2) + b_base;
                    uint32_t r0, r1, r2, r3;
                    ldsm_x4t(r0, r1, r2, r3, w_tap + swz(off));
                    bf[p * 2 + 0][0] = r0; bf[p * 2 + 0][1] = r1;
                    bf[p * 2 + 1][0] = r2; bf[p * 2 + 1][1] = r3;
                }
#pragma unroll
                for (int mt = 0; mt < 4; mt++) {
                    uint32_t af[4];
                    const uint32_t off = a_row0 + (uint32_t)(mt * 16 * 128) + (uint32_t)(cc * 32) + a_base;
                    ldsm_x4(af[0], af[1], af[2], af[3], xs_addr + swz(off));
#pragma unroll
                    for (int nt = 0; nt < 4; nt++)
                        mma16816(acc[mt][nt], af, bf[nt]);
                }
            }
        }
        __syncthreads();   // all warps done reading xs before next stage

        // ---- epilogue: bias + direct STG
#pragma unroll
        for (int mt = 0; mt < 4; mt++) {
            const int trow = t0 + warp_m * 64 + mt * 16 + g;
#pragma unroll
            for (int half = 0; half < 2; half++) {
                const int t = trow + half * 8;
                if (t < TOUT) {
                    float* o = out + ((size_t)b * TOUT + t) * NF;
#pragma unroll
                    for (int nt = 0; nt < 4; nt++) {
                        const int f = warp_n * 32 + nt * 8 + tg * 2;
                        const float2 bv = *(const float2*)(base + BIAS_OFF + f * 4);
                        float2 v;
                        v.x = acc[mt][nt][half * 2 + 0] + bv.x;
                        v.y = acc[mt][nt][half * 2 + 1] + bv.y;
                        *(float2*)(o + f) = v;
                    }
                }
            }
        }
    }
}

extern "C" void kernel_launch(void* const* d_in, const int* in_sizes, int n_in,
                              void* d_out, int out_size) {
    const float* x    = (const float*)d_in[0];
    const float* w    = (const float*)d_in[1];
    const float* bias = (const float*)d_in[2];
    float* out = (float*)d_out;

    cudaFuncSetAttribute(conv_hmma_kernel, cudaFuncAttributeMaxDynamicSharedMemorySize, SMEM_BYTES);

    prep_w_kernel<<<(NF * KW * CIN + 255) / 256, 256>>>(w);
    conv_hmma_kernel<<<296, 256, SMEM_BYTES>>>(x, bias, out);
}